// round 1
// baseline (speedup 1.0000x reference)
#include <cuda_runtime.h>
#include <cuda_bf16.h>
#include <cstdint>

// FirstSpikeDetector: out[b][t] = 1 iff spike_train[b][t] is the first nonzero
// in row b, else 0. Input values are exact 0.0f / 1.0f.
//
// Strategy: one warp per row.
//   Phase 1: early-exit scan in 128-element chunks (32 lanes x float4) to find
//            the first nonzero index. ~10% firing rate => almost always found
//            in the first chunk (P(miss) ~ 1.4e-6), so we read ~512B/row.
//   Phase 2: write the whole 2048-float row as zeros via float4 stores,
//            injecting 1.0f into the vector holding the first-spike index.
// Total traffic ~ 128MB write + ~8MB read => write-bandwidth bound.

static constexpr int T = 2048;          // time steps per row
static constexpr int TV = T / 4;        // float4s per row (512)
static constexpr int CHUNK = 128;       // elements scanned per warp iteration

__global__ void __launch_bounds__(256)
first_spike_kernel(const float* __restrict__ in, float* __restrict__ out, int rows)
{
    const int gtid   = blockIdx.x * blockDim.x + threadIdx.x;
    const int warp   = gtid >> 5;
    const int lane   = gtid & 31;
    if (warp >= rows) return;

    const float4* __restrict__ row_in  = reinterpret_cast<const float4*>(in)  + (size_t)warp * TV;
    float4* __restrict__       row_out = reinterpret_cast<float4*>(out)       + (size_t)warp * TV;

    // ---- Phase 1: find first nonzero index (early exit) ----
    int first = T;  // sentinel: no spike in row
    #pragma unroll 1
    for (int base = 0; base < T; base += CHUNK) {
        float4 v = row_in[(base >> 2) + lane];
        bool any = (v.x != 0.0f) | (v.y != 0.0f) | (v.z != 0.0f) | (v.w != 0.0f);
        unsigned m = __ballot_sync(0xffffffffu, any);
        if (m) {
            int src = __ffs(m) - 1;           // first lane with a nonzero
            int sub = 0;
            if (v.x != 0.0f)      sub = 0;
            else if (v.y != 0.0f) sub = 1;
            else if (v.z != 0.0f) sub = 2;
            else                  sub = 3;
            sub = __shfl_sync(0xffffffffu, sub, src);
            first = base + (src << 2) + sub;
            break;
        }
    }

    // ---- Phase 2: write one-hot row with float4 stores ----
    const int fq = first >> 2;   // which float4 holds the spike (T/4=512 if none)
    const int fr = first & 3;

    #pragma unroll
    for (int i = lane; i < TV; i += 32) {
        float4 z = make_float4(0.0f, 0.0f, 0.0f, 0.0f);
        if (i == fq) {
            if      (fr == 0) z.x = 1.0f;
            else if (fr == 1) z.y = 1.0f;
            else if (fr == 2) z.z = 1.0f;
            else              z.w = 1.0f;
        }
        row_out[i] = z;
    }
}

extern "C" void kernel_launch(void* const* d_in, const int* in_sizes, int n_in,
                              void* d_out, int out_size)
{
    const float* in = (const float*)d_in[0];
    float* out = (float*)d_out;

    const int rows = in_sizes[0] / T;           // 16384
    const int threads = 256;                    // 8 warps/block
    const int warps_needed = rows;
    const int blocks = (warps_needed * 32 + threads - 1) / threads;  // 2048

    first_spike_kernel<<<blocks, threads>>>(in, out, rows);
}